// round 2
// baseline (speedup 1.0000x reference)
#include <cuda_runtime.h>
#include <math_constants.h>

#define BB 4
#define SS 2048
#define DD 1024
#define HH 16
#define DH 64
#define MM (BB*SS)          // 8192 rows

// Scratch (allocation-free rule: __device__ globals)
__device__ float g_Q[MM*DD];
__device__ float g_K[MM*DD];
__device__ float g_V[MM*DD];
__device__ float g_ctx[MM*DD];

// ---------------------------------------------------------------------------
// SGEMM: C[M,N] = A[M,K] @ B[K,N], all row-major fp32.
// Tile 64x64, BK=16, 256 threads, 4x4 microtile, A staged transposed so both
// compute operands are LDS.128 (conflict-free reads; 4-way conflict on the
// one-time transposed A stores, amortized).
// ---------------------------------------------------------------------------
__global__ __launch_bounds__(256) void sgemm64(
    const float* __restrict__ A, const float* __restrict__ Bm,
    float* __restrict__ C, int M, int N, int K)
{
    __shared__ float As[16][64];   // As[k][m]
    __shared__ float Bs[16][64];   // Bs[k][n]

    const int tid = threadIdx.x;
    const int tx = tid & 15;       // 0..15 -> n microtile
    const int ty = tid >> 4;       // 0..15 -> m microtile
    const int row0 = blockIdx.y * 64;
    const int col0 = blockIdx.x * 64;

    const int am  = tid >> 2;            // 0..63
    const int ak4 = (tid & 3) * 4;       // 0,4,8,12
    const int bk  = tid >> 4;            // 0..15
    const int bn4 = (tid & 15) * 4;      // 0..60

    float acc[4][4];
    #pragma unroll
    for (int i = 0; i < 4; i++)
        #pragma unroll
        for (int j = 0; j < 4; j++) acc[i][j] = 0.f;

    for (int kk = 0; kk < K; kk += 16) {
        float4 av = *(const float4*)&A[(size_t)(row0 + am) * K + kk + ak4];
        As[ak4 + 0][am] = av.x;
        As[ak4 + 1][am] = av.y;
        As[ak4 + 2][am] = av.z;
        As[ak4 + 3][am] = av.w;
        float4 bv = *(const float4*)&Bm[(size_t)(kk + bk) * N + col0 + bn4];
        *(float4*)&Bs[bk][bn4] = bv;
        __syncthreads();

        #pragma unroll
        for (int k = 0; k < 16; k++) {
            float4 a4 = *(float4*)&As[k][ty * 4];
            float4 b4 = *(float4*)&Bs[k][tx * 4];
            float a[4] = {a4.x, a4.y, a4.z, a4.w};
            float b[4] = {b4.x, b4.y, b4.z, b4.w};
            #pragma unroll
            for (int i = 0; i < 4; i++)
                #pragma unroll
                for (int j = 0; j < 4; j++)
                    acc[i][j] = fmaf(a[i], b[j], acc[i][j]);
        }
        __syncthreads();
    }

    #pragma unroll
    for (int i = 0; i < 4; i++) {
        float4 v = {acc[i][0], acc[i][1], acc[i][2], acc[i][3]};
        *(float4*)&C[(size_t)(row0 + ty * 4 + i) * N + col0 + tx * 4] = v;
    }
}

// ---------------------------------------------------------------------------
// Flash attention, fp32, per (b,h) head slice of the [B,S,D] Q/K/V buffers.
// BM=BN=64, DH=64. Online softmax. ctx written head-interleaved -> no
// transpose kernels needed. Scale = 1/sqrt(D) = 1/32 (NOT 1/sqrt(dh)).
// ---------------------------------------------------------------------------
#define ST 68   // shared row stride (floats); 16B aligned, breaks worst conflicts

__global__ __launch_bounds__(256) void attn64(
    const float* __restrict__ Q, const float* __restrict__ K,
    const float* __restrict__ V, float* __restrict__ ctx)
{
    extern __shared__ float smem[];
    float (*Qs)[ST] = (float(*)[ST])(smem);                 // Qs[d][m]
    float (*Ks)[ST] = (float(*)[ST])(smem + 64 * ST);       // Ks[d][n]
    float (*Vs)[ST] = (float(*)[ST])(smem + 2 * 64 * ST);   // Vs[j][dv]
    float (*Ps)[ST] = (float(*)[ST])(smem + 3 * 64 * ST);   // Ps[j][m]

    const int tid = threadIdx.x;
    const int tx = tid & 15;
    const int ty = tid >> 4;

    const int qt = blockIdx.x;             // q tile (0..31)
    const int bh = blockIdx.y;             // 0..63
    const int b  = bh / HH;
    const int h  = bh % HH;

    const size_t baseRow = (size_t)b * SS;
    const int    hcol    = h * DH;
    const float  scale   = 0.03125f;       // 1/sqrt(1024)

    // Load Q tile transposed: Qs[d][m]
    #pragma unroll
    for (int i = 0; i < 4; i++) {
        int f4 = tid + 256 * i;            // 0..1023
        int m  = f4 >> 4;                  // 0..63
        int d4 = (f4 & 15) * 4;            // 0..60
        float4 qv = *(const float4*)&Q[(baseRow + qt * 64 + m) * DD + hcol + d4];
        Qs[d4 + 0][m] = qv.x;
        Qs[d4 + 1][m] = qv.y;
        Qs[d4 + 2][m] = qv.z;
        Qs[d4 + 3][m] = qv.w;
    }

    float o[4][4];
    float mrow[4], lrow[4];
    #pragma unroll
    for (int i = 0; i < 4; i++) {
        mrow[i] = -CUDART_INF_F;
        lrow[i] = 0.f;
        #pragma unroll
        for (int j = 0; j < 4; j++) o[i][j] = 0.f;
    }
    __syncthreads();

    for (int kt = 0; kt < SS / 64; kt++) {
        // Load K tile (transposed) and V tile (row-major)
        #pragma unroll
        for (int i = 0; i < 4; i++) {
            int f4 = tid + 256 * i;
            int n  = f4 >> 4;
            int d4 = (f4 & 15) * 4;
            size_t gro = (baseRow + kt * 64 + n) * DD + hcol + d4;
            float4 kv = *(const float4*)&K[gro];
            Ks[d4 + 0][n] = kv.x;
            Ks[d4 + 1][n] = kv.y;
            Ks[d4 + 2][n] = kv.z;
            Ks[d4 + 3][n] = kv.w;
            float4 vv = *(const float4*)&V[gro];
            *(float4*)&Vs[n][d4] = vv;
        }
        __syncthreads();

        // GEMM1: s = Qtile @ Ktile^T
        float s[4][4];
        #pragma unroll
        for (int i = 0; i < 4; i++)
            #pragma unroll
            for (int j = 0; j < 4; j++) s[i][j] = 0.f;

        #pragma unroll 8
        for (int d = 0; d < 64; d++) {
            float4 a4 = *(float4*)&Qs[d][ty * 4];
            float4 b4 = *(float4*)&Ks[d][tx * 4];
            float a[4] = {a4.x, a4.y, a4.z, a4.w};
            float bq[4] = {b4.x, b4.y, b4.z, b4.w};
            #pragma unroll
            for (int i = 0; i < 4; i++)
                #pragma unroll
                for (int j = 0; j < 4; j++)
                    s[i][j] = fmaf(a[i], bq[j], s[i][j]);
        }

        // Online softmax update (rows owned redundantly across the 16 tx lanes)
        #pragma unroll
        for (int i = 0; i < 4; i++) {
            float rmax = -CUDART_INF_F;
            #pragma unroll
            for (int j = 0; j < 4; j++) {
                s[i][j] *= scale;
                rmax = fmaxf(rmax, s[i][j]);
            }
            #pragma unroll
            for (int off = 8; off >= 1; off >>= 1)
                rmax = fmaxf(rmax, __shfl_xor_sync(0xffffffffu, rmax, off, 16));

            float mnew = fmaxf(mrow[i], rmax);
            float corr = __expf(mrow[i] - mnew);
            float rsum = 0.f;
            #pragma unroll
            for (int j = 0; j < 4; j++) {
                s[i][j] = __expf(s[i][j] - mnew);
                rsum += s[i][j];
            }
            #pragma unroll
            for (int off = 8; off >= 1; off >>= 1)
                rsum += __shfl_xor_sync(0xffffffffu, rsum, off, 16);

            lrow[i] = lrow[i] * corr + rsum;
            mrow[i] = mnew;
            #pragma unroll
            for (int j = 0; j < 4; j++) o[i][j] *= corr;
        }

        // Stage P transposed: Ps[j][m]
        #pragma unroll
        for (int i = 0; i < 4; i++)
            #pragma unroll
            for (int j = 0; j < 4; j++)
                Ps[tx * 4 + j][ty * 4 + i] = s[i][j];
        __syncthreads();

        // GEMM2: o += Ptile @ Vtile
        #pragma unroll 8
        for (int j = 0; j < 64; j++) {
            float4 a4 = *(float4*)&Ps[j][ty * 4];
            float4 b4 = *(float4*)&Vs[j][tx * 4];
            float a[4] = {a4.x, a4.y, a4.z, a4.w};
            float bv[4] = {b4.x, b4.y, b4.z, b4.w};
            #pragma unroll
            for (int i = 0; i < 4; i++)
                #pragma unroll
                for (int jj = 0; jj < 4; jj++)
                    o[i][jj] = fmaf(a[i], bv[jj], o[i][jj]);
        }
        __syncthreads();   // before next tile overwrites Ks/Vs/Ps
    }

    // Finalize and write ctx (head-interleaved layout)
    #pragma unroll
    for (int i = 0; i < 4; i++) {
        float inv = 1.f / lrow[i];
        float4 v = {o[i][0] * inv, o[i][1] * inv, o[i][2] * inv, o[i][3] * inv};
        *(float4*)&ctx[(baseRow + qt * 64 + ty * 4 + i) * DD + hcol + tx * 4] = v;
    }
}

// ---------------------------------------------------------------------------
extern "C" void kernel_launch(void* const* d_in, const int* in_sizes, int n_in,
                              void* d_out, int out_size)
{
    const float* x  = (const float*)d_in[0];
    const float* WQ = (const float*)d_in[1];
    const float* WK = (const float*)d_in[2];
    const float* WV = (const float*)d_in[3];
    const float* WO = (const float*)d_in[4];
    float* out = (float*)d_out;

    float *Qp, *Kp, *Vp, *Cp;
    cudaGetSymbolAddress((void**)&Qp, g_Q);
    cudaGetSymbolAddress((void**)&Kp, g_K);
    cudaGetSymbolAddress((void**)&Vp, g_V);
    cudaGetSymbolAddress((void**)&Cp, g_ctx);

    const int smemAttn = 4 * 64 * ST * (int)sizeof(float);   // 69,632 B
    cudaFuncSetAttribute(attn64, cudaFuncAttributeMaxDynamicSharedMemorySize, smemAttn);

    dim3 gProj(DD / 64, MM / 64);   // (16, 128)
    sgemm64<<<gProj, 256>>>(x, WQ, Qp, MM, DD, DD);
    sgemm64<<<gProj, 256>>>(x, WK, Kp, MM, DD, DD);
    sgemm64<<<gProj, 256>>>(x, WV, Vp, MM, DD, DD);

    dim3 gAttn(SS / 64, BB * HH);   // (32, 64)
    attn64<<<gAttn, 256, smemAttn>>>(Qp, Kp, Vp, Cp);

    sgemm64<<<gProj, 256>>>(Cp, WO, out, MM, DD, DD);
}

// round 9
// speedup vs baseline: 1.4976x; 1.4976x over previous
#include <cuda_runtime.h>
#include <math_constants.h>
#include <cstdint>

#define BB 4
#define SS 2048
#define DD 1024
#define HH 16
#define DH 64
#define MM (BB*SS)          // 8192 rows

// Scratch (allocation-free rule: __device__ globals)
__device__ float g_Q[MM*DD];
__device__ float g_K[MM*DD];
__device__ float g_V[MM*DD];
__device__ float g_ctx[MM*DD];

// ---------------------------------------------------------------------------
// Helpers (sm_80-era PTX only: cp.async + mma.sync — valid on sm_103 target)
// ---------------------------------------------------------------------------
__device__ __forceinline__ uint32_t smem_addr(const void* p) {
    return (uint32_t)__cvta_generic_to_shared(p);
}
__device__ __forceinline__ void cp_async16(uint32_t saddr, const void* g) {
    asm volatile("cp.async.cg.shared.global [%0], [%1], 16;" :: "r"(saddr), "l"(g));
}
#define CP_COMMIT() asm volatile("cp.async.commit_group;" ::: "memory")
#define CP_WAIT(n)  asm volatile("cp.async.wait_group %0;" :: "n"(n) : "memory")

__device__ __forceinline__ uint32_t f2tf32(float f) {
    uint32_t r; asm("cvt.rna.tf32.f32 %0, %1;" : "=r"(r) : "f"(f)); return r;
}
__device__ __forceinline__ void mma_tf32(float c[4],
    uint32_t a0, uint32_t a1, uint32_t a2, uint32_t a3, uint32_t b0, uint32_t b1)
{
    asm volatile(
        "mma.sync.aligned.m16n8k8.row.col.f32.tf32.tf32.f32 "
        "{%0,%1,%2,%3}, {%4,%5,%6,%7}, {%8,%9}, {%0,%1,%2,%3};"
        : "+f"(c[0]), "+f"(c[1]), "+f"(c[2]), "+f"(c[3])
        : "r"(a0), "r"(a1), "r"(a2), "r"(a3), "r"(b0), "r"(b1));
}

// ---------------------------------------------------------------------------
// tf32 tensor-core GEMM: C[M,N] = A[M,K] @ B[K,N], fp32 in/out, K=N=1024.
// 128x128 tile, BK=16, 256 threads (8 warps of 64x32), 3-stage cp.async.
// SMEM strides chosen conflict-free for the exact mma fragment read patterns:
//   A stride 20 floats (20*gid + tig mod 32 -> 32 distinct banks)
//   B stride 136 floats (136*tig + gid mod 32 -> 32 distinct banks)
// ---------------------------------------------------------------------------
#define GBK 16
#define ASTR 20
#define BSTR 136
#define STAGES 3
#define A_BYTES (128*ASTR*4)          // 10240
#define B_BYTES (GBK*BSTR*4)          // 8704
#define STAGE_BYTES (A_BYTES + B_BYTES)
#define GSMEM (STAGES*STAGE_BYTES)    // 56832

__global__ __launch_bounds__(256) void gemm_mma(
    const float* __restrict__ A, const float* __restrict__ B,
    float* __restrict__ C)
{
    extern __shared__ char smem[];
    const int tid   = threadIdx.x;
    const int wid   = tid >> 5;
    const int lane  = tid & 31;
    const int gid   = lane >> 2;      // group (row) id 0..7
    const int tig   = lane & 3;       // thread-in-group 0..3
    const int wm    = wid & 1;        // warp m-tile (0..1), 64 rows each
    const int wn    = wid >> 1;       // warp n-tile (0..3), 32 cols each
    const int row0  = blockIdx.y * 128;
    const int col0  = blockIdx.x * 128;

    float c[4][4][4];
    #pragma unroll
    for (int i = 0; i < 4; i++)
        #pragma unroll
        for (int j = 0; j < 4; j++)
            #pragma unroll
            for (int r = 0; r < 4; r++) c[i][j][r] = 0.f;

    auto load_tile = [&](int buf, int kk) {
        char* base = smem + buf * STAGE_BYTES;
        #pragma unroll
        for (int i = 0; i < 2; i++) {
            int f  = tid + 256 * i;       // 0..511
            int r  = f >> 2;              // 0..127
            int k4 = (f & 3) * 4;
            cp_async16(smem_addr(base + (r * ASTR + k4) * 4),
                       &A[(size_t)(row0 + r) * DD + kk + k4]);
        }
        #pragma unroll
        for (int i = 0; i < 2; i++) {
            int f  = tid + 256 * i;
            int kr = f >> 5;              // 0..15
            int c4 = (f & 31) * 4;
            cp_async16(smem_addr(base + A_BYTES + (kr * BSTR + c4) * 4),
                       &B[(size_t)(kk + kr) * DD + col0 + c4]);
        }
    };

    const int NKT = DD / GBK;             // 64
    // Prologue: issue first STAGES-1 tiles
    #pragma unroll
    for (int s = 0; s < STAGES - 1; s++) { load_tile(s, s * GBK); CP_COMMIT(); }

    for (int kt = 0; kt < NKT; kt++) {
        CP_WAIT(STAGES - 2);              // tile kt resident
        __syncthreads();

        // Issue tile kt+2 into the buffer freed by compute(kt-1)
        if (kt + STAGES - 1 < NKT) load_tile((kt + STAGES - 1) % STAGES,
                                             (kt + STAGES - 1) * GBK);
        CP_COMMIT();                      // empty groups at tail keep accounting

        const int buf = kt % STAGES;
        const float* As = (const float*)(smem + buf * STAGE_BYTES);
        const float* Bs = (const float*)(smem + buf * STAGE_BYTES + A_BYTES);

        #pragma unroll
        for (int s = 0; s < 2; s++) {     // two k8 steps per BK16
            uint32_t af[4][4], bf[4][2];
            #pragma unroll
            for (int i = 0; i < 4; i++) {
                int br = wm * 64 + i * 16;
                af[i][0] = f2tf32(As[(br + gid    ) * ASTR + s * 8 + tig    ]);
                af[i][1] = f2tf32(As[(br + gid + 8) * ASTR + s * 8 + tig    ]);
                af[i][2] = f2tf32(As[(br + gid    ) * ASTR + s * 8 + tig + 4]);
                af[i][3] = f2tf32(As[(br + gid + 8) * ASTR + s * 8 + tig + 4]);
            }
            #pragma unroll
            for (int j = 0; j < 4; j++) {
                int bc = wn * 32 + j * 8;
                bf[j][0] = f2tf32(Bs[(s * 8 + tig    ) * BSTR + bc + gid]);
                bf[j][1] = f2tf32(Bs[(s * 8 + tig + 4) * BSTR + bc + gid]);
            }
            #pragma unroll
            for (int i = 0; i < 4; i++)
                #pragma unroll
                for (int j = 0; j < 4; j++)
                    mma_tf32(c[i][j], af[i][0], af[i][1], af[i][2], af[i][3],
                             bf[j][0], bf[j][1]);
        }
        __syncthreads();
    }

    // Epilogue: direct float2 stores (32B sectors, fully used)
    #pragma unroll
    for (int i = 0; i < 4; i++) {
        #pragma unroll
        for (int j = 0; j < 4; j++) {
            int r  = row0 + wm * 64 + i * 16 + gid;
            int cc = col0 + wn * 32 + j * 8 + tig * 2;
            float2 v0 = {c[i][j][0], c[i][j][1]};
            float2 v1 = {c[i][j][2], c[i][j][3]};
            *(float2*)&C[(size_t)r * DD + cc]       = v0;
            *(float2*)&C[(size_t)(r + 8) * DD + cc] = v1;
        }
    }
}

// ---------------------------------------------------------------------------
// Flash attention, fp32 SIMT (validated in R2)
// ---------------------------------------------------------------------------
#define ST 68

__global__ __launch_bounds__(256) void attn64(
    const float* __restrict__ Q, const float* __restrict__ K,
    const float* __restrict__ V, float* __restrict__ ctx)
{
    extern __shared__ float smemf[];
    float (*Qs)[ST] = (float(*)[ST])(smemf);
    float (*Ks)[ST] = (float(*)[ST])(smemf + 64 * ST);
    float (*Vs)[ST] = (float(*)[ST])(smemf + 2 * 64 * ST);
    float (*Ps)[ST] = (float(*)[ST])(smemf + 3 * 64 * ST);

    const int tid = threadIdx.x;
    const int tx = tid & 15;
    const int ty = tid >> 4;

    const int qt = blockIdx.x;
    const int bh = blockIdx.y;
    const int b  = bh / HH;
    const int h  = bh % HH;

    const size_t baseRow = (size_t)b * SS;
    const int    hcol    = h * DH;
    const float  scale   = 0.03125f;       // 1/sqrt(1024)

    #pragma unroll
    for (int i = 0; i < 4; i++) {
        int f4 = tid + 256 * i;
        int m  = f4 >> 4;
        int d4 = (f4 & 15) * 4;
        float4 qv = *(const float4*)&Q[(baseRow + qt * 64 + m) * DD + hcol + d4];
        Qs[d4 + 0][m] = qv.x;
        Qs[d4 + 1][m] = qv.y;
        Qs[d4 + 2][m] = qv.z;
        Qs[d4 + 3][m] = qv.w;
    }

    float o[4][4];
    float mrow[4], lrow[4];
    #pragma unroll
    for (int i = 0; i < 4; i++) {
        mrow[i] = -CUDART_INF_F;
        lrow[i] = 0.f;
        #pragma unroll
        for (int j = 0; j < 4; j++) o[i][j] = 0.f;
    }
    __syncthreads();

    for (int kt = 0; kt < SS / 64; kt++) {
        #pragma unroll
        for (int i = 0; i < 4; i++) {
            int f4 = tid + 256 * i;
            int n  = f4 >> 4;
            int d4 = (f4 & 15) * 4;
            size_t gro = (baseRow + kt * 64 + n) * DD + hcol + d4;
            float4 kv = *(const float4*)&K[gro];
            Ks[d4 + 0][n] = kv.x;
            Ks[d4 + 1][n] = kv.y;
            Ks[d4 + 2][n] = kv.z;
            Ks[d4 + 3][n] = kv.w;
            float4 vv = *(const float4*)&V[gro];
            *(float4*)&Vs[n][d4] = vv;
        }
        __syncthreads();

        float s[4][4];
        #pragma unroll
        for (int i = 0; i < 4; i++)
            #pragma unroll
            for (int j = 0; j < 4; j++) s[i][j] = 0.f;

        #pragma unroll 8
        for (int d = 0; d < 64; d++) {
            float4 a4 = *(float4*)&Qs[d][ty * 4];
            float4 b4 = *(float4*)&Ks[d][tx * 4];
            float a[4] = {a4.x, a4.y, a4.z, a4.w};
            float bq[4] = {b4.x, b4.y, b4.z, b4.w};
            #pragma unroll
            for (int i = 0; i < 4; i++)
                #pragma unroll
                for (int j = 0; j < 4; j++)
                    s[i][j] = fmaf(a[i], bq[j], s[i][j]);
        }

        #pragma unroll
        for (int i = 0; i < 4; i++) {
            float rmax = -CUDART_INF_F;
            #pragma unroll
            for (int j = 0; j < 4; j++) {
                s[i][j] *= scale;
                rmax = fmaxf(rmax, s[i][j]);
            }
            #pragma unroll
            for (int off = 8; off >= 1; off >>= 1)
                rmax = fmaxf(rmax, __shfl_xor_sync(0xffffffffu, rmax, off, 16));

            float mnew = fmaxf(mrow[i], rmax);
            float corr = __expf(mrow[i] - mnew);
            float rsum = 0.f;
            #pragma unroll
            for (int j = 0; j < 4; j++) {
                s[i][j] = __expf(s[i][j] - mnew);
                rsum += s[i][j];
            }
            #pragma unroll
            for (int off = 8; off >= 1; off >>= 1)
                rsum += __shfl_xor_sync(0xffffffffu, rsum, off, 16);

            lrow[i] = lrow[i] * corr + rsum;
            mrow[i] = mnew;
            #pragma unroll
            for (int j = 0; j < 4; j++) o[i][j] *= corr;
        }

        #pragma unroll
        for (int i = 0; i < 4; i++)
            #pragma unroll
            for (int j = 0; j < 4; j++)
                Ps[tx * 4 + j][ty * 4 + i] = s[i][j];
        __syncthreads();

        #pragma unroll 8
        for (int j = 0; j < 64; j++) {
            float4 a4 = *(float4*)&Ps[j][ty * 4];
            float4 b4 = *(float4*)&Vs[j][tx * 4];
            float a[4] = {a4.x, a4.y, a4.z, a4.w};
            float bv[4] = {b4.x, b4.y, b4.z, b4.w};
            #pragma unroll
            for (int i = 0; i < 4; i++)
                #pragma unroll
                for (int jj = 0; jj < 4; jj++)
                    o[i][jj] = fmaf(a[i], bv[jj], o[i][jj]);
        }
        __syncthreads();
    }

    #pragma unroll
    for (int i = 0; i < 4; i++) {
        float inv = 1.f / lrow[i];
        float4 v = {o[i][0] * inv, o[i][1] * inv, o[i][2] * inv, o[i][3] * inv};
        *(float4*)&ctx[(baseRow + qt * 64 + ty * 4 + i) * DD + hcol + tx * 4] = v;
    }
}

// ---------------------------------------------------------------------------
extern "C" void kernel_launch(void* const* d_in, const int* in_sizes, int n_in,
                              void* d_out, int out_size)
{
    const float* x  = (const float*)d_in[0];
    const float* WQ = (const float*)d_in[1];
    const float* WK = (const float*)d_in[2];
    const float* WV = (const float*)d_in[3];
    const float* WO = (const float*)d_in[4];
    float* out = (float*)d_out;

    float *Qp, *Kp, *Vp, *Cp;
    cudaGetSymbolAddress((void**)&Qp, g_Q);
    cudaGetSymbolAddress((void**)&Kp, g_K);
    cudaGetSymbolAddress((void**)&Vp, g_V);
    cudaGetSymbolAddress((void**)&Cp, g_ctx);

    const int smemAttn = 4 * 64 * ST * (int)sizeof(float);   // 69,632 B
    cudaFuncSetAttribute(attn64,   cudaFuncAttributeMaxDynamicSharedMemorySize, smemAttn);
    cudaFuncSetAttribute(gemm_mma, cudaFuncAttributeMaxDynamicSharedMemorySize, GSMEM);

    dim3 gg(DD / 128, MM / 128);    // (8, 64)
    gemm_mma<<<gg, 256, GSMEM>>>(x, WQ, Qp);
    gemm_mma<<<gg, 256, GSMEM>>>(x, WK, Kp);
    gemm_mma<<<gg, 256, GSMEM>>>(x, WV, Vp);

    dim3 gAttn(SS / 64, BB * HH);   // (32, 64)
    attn64<<<gAttn, 256, smemAttn>>>(Qp, Kp, Vp, Cp);

    gemm_mma<<<gg, 256, GSMEM>>>(Cp, WO, out);
}

// round 10
// speedup vs baseline: 2.0557x; 1.3727x over previous
#include <cuda_runtime.h>
#include <math_constants.h>
#include <cstdint>

#define BB 4
#define SS 2048
#define DD 1024
#define HH 16
#define DH 64
#define MM (BB*SS)          // 8192 rows

// Scratch (allocation-free rule: __device__ globals)
__device__ float g_Q[MM*DD];
__device__ float g_K[MM*DD];
__device__ float g_V[MM*DD];
__device__ float g_ctx[MM*DD];

// ---------------------------------------------------------------------------
// Helpers (sm_80-era PTX: cp.async + mma.sync — valid on sm_103 target)
// ---------------------------------------------------------------------------
__device__ __forceinline__ uint32_t smem_addr(const void* p) {
    return (uint32_t)__cvta_generic_to_shared(p);
}
__device__ __forceinline__ void cp_async16(uint32_t saddr, const void* g) {
    asm volatile("cp.async.cg.shared.global [%0], [%1], 16;" :: "r"(saddr), "l"(g));
}
#define CP_COMMIT() asm volatile("cp.async.commit_group;" ::: "memory")
#define CP_WAIT(n)  asm volatile("cp.async.wait_group %0;" :: "n"(n) : "memory")

__device__ __forceinline__ uint32_t f2tf32(float f) {
    uint32_t r; asm("cvt.rna.tf32.f32 %0, %1;" : "=r"(r) : "f"(f)); return r;
}
__device__ __forceinline__ void mma_tf32(float c[4],
    uint32_t a0, uint32_t a1, uint32_t a2, uint32_t a3, uint32_t b0, uint32_t b1)
{
    asm volatile(
        "mma.sync.aligned.m16n8k8.row.col.f32.tf32.tf32.f32 "
        "{%0,%1,%2,%3}, {%4,%5,%6,%7}, {%8,%9}, {%0,%1,%2,%3};"
        : "+f"(c[0]), "+f"(c[1]), "+f"(c[2]), "+f"(c[3])
        : "r"(a0), "r"(a1), "r"(a2), "r"(a3), "r"(b0), "r"(b1));
}

// ---------------------------------------------------------------------------
// tf32 tensor-core GEMM (unchanged from R9): C[M,N] = A[M,K] @ B[K,N]
// ---------------------------------------------------------------------------
#define GBK 16
#define ASTR 20
#define BSTR 136
#define STAGES 3
#define A_BYTES (128*ASTR*4)
#define B_BYTES (GBK*BSTR*4)
#define STAGE_BYTES (A_BYTES + B_BYTES)
#define GSMEM (STAGES*STAGE_BYTES)

__global__ __launch_bounds__(256) void gemm_mma(
    const float* __restrict__ A, const float* __restrict__ B,
    float* __restrict__ C)
{
    extern __shared__ char smem[];
    const int tid   = threadIdx.x;
    const int wid   = tid >> 5;
    const int lane  = tid & 31;
    const int gid   = lane >> 2;
    const int tig   = lane & 3;
    const int wm    = wid & 1;
    const int wn    = wid >> 1;
    const int row0  = blockIdx.y * 128;
    const int col0  = blockIdx.x * 128;

    float c[4][4][4];
    #pragma unroll
    for (int i = 0; i < 4; i++)
        #pragma unroll
        for (int j = 0; j < 4; j++)
            #pragma unroll
            for (int r = 0; r < 4; r++) c[i][j][r] = 0.f;

    auto load_tile = [&](int buf, int kk) {
        char* base = smem + buf * STAGE_BYTES;
        #pragma unroll
        for (int i = 0; i < 2; i++) {
            int f  = tid + 256 * i;
            int r  = f >> 2;
            int k4 = (f & 3) * 4;
            cp_async16(smem_addr(base + (r * ASTR + k4) * 4),
                       &A[(size_t)(row0 + r) * DD + kk + k4]);
        }
        #pragma unroll
        for (int i = 0; i < 2; i++) {
            int f  = tid + 256 * i;
            int kr = f >> 5;
            int c4 = (f & 31) * 4;
            cp_async16(smem_addr(base + A_BYTES + (kr * BSTR + c4) * 4),
                       &B[(size_t)(kk + kr) * DD + col0 + c4]);
        }
    };

    const int NKT = DD / GBK;
    #pragma unroll
    for (int s = 0; s < STAGES - 1; s++) { load_tile(s, s * GBK); CP_COMMIT(); }

    for (int kt = 0; kt < NKT; kt++) {
        CP_WAIT(STAGES - 2);
        __syncthreads();

        if (kt + STAGES - 1 < NKT) load_tile((kt + STAGES - 1) % STAGES,
                                             (kt + STAGES - 1) * GBK);
        CP_COMMIT();

        const int buf = kt % STAGES;
        const float* As = (const float*)(smem + buf * STAGE_BYTES);
        const float* Bs = (const float*)(smem + buf * STAGE_BYTES + A_BYTES);

        #pragma unroll
        for (int s = 0; s < 2; s++) {
            uint32_t af[4][4], bf[4][2];
            #pragma unroll
            for (int i = 0; i < 4; i++) {
                int br = wm * 64 + i * 16;
                af[i][0] = f2tf32(As[(br + gid    ) * ASTR + s * 8 + tig    ]);
                af[i][1] = f2tf32(As[(br + gid + 8) * ASTR + s * 8 + tig    ]);
                af[i][2] = f2tf32(As[(br + gid    ) * ASTR + s * 8 + tig + 4]);
                af[i][3] = f2tf32(As[(br + gid + 8) * ASTR + s * 8 + tig + 4]);
            }
            #pragma unroll
            for (int j = 0; j < 4; j++) {
                int bc = wn * 32 + j * 8;
                bf[j][0] = f2tf32(Bs[(s * 8 + tig    ) * BSTR + bc + gid]);
                bf[j][1] = f2tf32(Bs[(s * 8 + tig + 4) * BSTR + bc + gid]);
            }
            #pragma unroll
            for (int i = 0; i < 4; i++)
                #pragma unroll
                for (int j = 0; j < 4; j++)
                    mma_tf32(c[i][j], af[i][0], af[i][1], af[i][2], af[i][3],
                             bf[j][0], bf[j][1]);
        }
        __syncthreads();
    }

    #pragma unroll
    for (int i = 0; i < 4; i++) {
        #pragma unroll
        for (int j = 0; j < 4; j++) {
            int r  = row0 + wm * 64 + i * 16 + gid;
            int cc = col0 + wn * 32 + j * 8 + tig * 2;
            float2 v0 = {c[i][j][0], c[i][j][1]};
            float2 v1 = {c[i][j][2], c[i][j][3]};
            *(float2*)&C[(size_t)r * DD + cc]       = v0;
            *(float2*)&C[(size_t)(r + 8) * DD + cc] = v1;
        }
    }
}

// ---------------------------------------------------------------------------
// Flash attention with tf32 mma.sync.
// BM=64 q-rows per CTA, 4 warps, each warp: 16 rows x 64 keys.
// K/V tiles (64x64) double-buffered cp.async. Q frags persistent in regs
// (pre-scaled by 1/sqrt(D)). P staged through reused Q smem (warp-private
// rows -> __syncwarp only). Online softmax in C-fragment registers.
//
// SMEM strides (floats):  Ks rows [key][d] stride 68 (68%32==4 -> gid*4+tig
// conflict-free); Vs [key][d] stride 72 (72%32==8 -> tig*8+gid); QP stride 68.
// ---------------------------------------------------------------------------
#define KSTR 68
#define VSTR 72
#define QSTR 68
#define KVSTAGE (64*KSTR + 64*VSTR)          // floats per stage = 8960
#define ASMEM ((2*KVSTAGE + 64*QSTR) * 4)    // 89088 bytes

__global__ __launch_bounds__(128, 2) void attn_mma(
    const float* __restrict__ Q, const float* __restrict__ K,
    const float* __restrict__ V, float* __restrict__ ctx)
{
    extern __shared__ float sm[];
    float* QP = sm + 2 * KVSTAGE;

    const int tid  = threadIdx.x;
    const int wid  = tid >> 5;
    const int lane = tid & 31;
    const int gid  = lane >> 2;
    const int tig  = lane & 3;

    const int qt = blockIdx.x;
    const int bh = blockIdx.y;
    const int b  = bh / HH;
    const int h  = bh % HH;
    const size_t baseRow = (size_t)b * SS;
    const int    hcol    = h * DH;

    // Prologue: Q tile + K/V tile 0 (one cp.async group)
    {
        #pragma unroll
        for (int i = 0; i < 8; i++) {
            int f  = tid + 128 * i;          // 0..1023
            int r  = f >> 4;                 // 0..63
            int c4 = (f & 15) * 4;           // 0..60
            cp_async16(smem_addr(&QP[r * QSTR + c4]),
                       &Q[(baseRow + qt * 64 + r) * DD + hcol + c4]);
            size_t gro = (baseRow + r) * DD + hcol + c4;   // kv tile 0: keys 0..63
            cp_async16(smem_addr(&sm[r * KSTR + c4]), &K[gro]);
            cp_async16(smem_addr(&sm[64 * KSTR + r * VSTR + c4]), &V[gro]);
        }
        CP_COMMIT();
    }
    CP_WAIT(0);
    __syncthreads();

    // Persistent Q fragments, pre-scaled by 1/sqrt(D)
    const float scale = 0.03125f;
    const int rA = wid * 16 + gid;
    uint32_t qf[8][4];
    #pragma unroll
    for (int ks = 0; ks < 8; ks++) {
        qf[ks][0] = f2tf32(QP[(rA    ) * QSTR + ks * 8 + tig    ] * scale);
        qf[ks][1] = f2tf32(QP[(rA + 8) * QSTR + ks * 8 + tig    ] * scale);
        qf[ks][2] = f2tf32(QP[(rA    ) * QSTR + ks * 8 + tig + 4] * scale);
        qf[ks][3] = f2tf32(QP[(rA + 8) * QSTR + ks * 8 + tig + 4] * scale);
    }
    // No sync needed: QP rows [wid*16, wid*16+16) are warp-private from here.

    float o[8][4];
    #pragma unroll
    for (int nt = 0; nt < 8; nt++)
        #pragma unroll
        for (int r = 0; r < 4; r++) o[nt][r] = 0.f;
    float mA = -CUDART_INF_F, mB = -CUDART_INF_F, lA = 0.f, lB = 0.f;

    const int NKT = SS / 64;   // 32
    for (int kt = 0; kt < NKT; kt++) {
        // Prefetch tile kt+1 (stage freed by compute kt-1; end-of-iter sync guards it)
        if (kt + 1 < NKT) {
            float* Kn = sm + ((kt + 1) & 1) * KVSTAGE;
            float* Vn = Kn + 64 * KSTR;
            #pragma unroll
            for (int i = 0; i < 8; i++) {
                int f  = tid + 128 * i;
                int r  = f >> 4;
                int c4 = (f & 15) * 4;
                size_t gro = (baseRow + (kt + 1) * 64 + r) * DD + hcol + c4;
                cp_async16(smem_addr(&Kn[r * KSTR + c4]), &K[gro]);
                cp_async16(smem_addr(&Vn[r * VSTR + c4]), &V[gro]);
            }
            CP_COMMIT();
            CP_WAIT(1);
        } else {
            CP_WAIT(0);
        }
        __syncthreads();

        const float* Ks = sm + (kt & 1) * KVSTAGE;
        const float* Vs = Ks + 64 * KSTR;

        // S = Q @ K^T  (scaled)
        float s[8][4];
        #pragma unroll
        for (int nt = 0; nt < 8; nt++)
            #pragma unroll
            for (int r = 0; r < 4; r++) s[nt][r] = 0.f;

        #pragma unroll
        for (int ks = 0; ks < 8; ks++) {
            #pragma unroll
            for (int nt = 0; nt < 8; nt++) {
                uint32_t b0 = f2tf32(Ks[(nt * 8 + gid) * KSTR + ks * 8 + tig    ]);
                uint32_t b1 = f2tf32(Ks[(nt * 8 + gid) * KSTR + ks * 8 + tig + 4]);
                mma_tf32(s[nt], qf[ks][0], qf[ks][1], qf[ks][2], qf[ks][3], b0, b1);
            }
        }

        // Online softmax (rows gid / gid+8; row spread across quad lanes)
        float rmaxA = -CUDART_INF_F, rmaxB = -CUDART_INF_F;
        #pragma unroll
        for (int nt = 0; nt < 8; nt++) {
            rmaxA = fmaxf(rmaxA, fmaxf(s[nt][0], s[nt][1]));
            rmaxB = fmaxf(rmaxB, fmaxf(s[nt][2], s[nt][3]));
        }
        rmaxA = fmaxf(rmaxA, __shfl_xor_sync(0xffffffffu, rmaxA, 1));
        rmaxA = fmaxf(rmaxA, __shfl_xor_sync(0xffffffffu, rmaxA, 2));
        rmaxB = fmaxf(rmaxB, __shfl_xor_sync(0xffffffffu, rmaxB, 1));
        rmaxB = fmaxf(rmaxB, __shfl_xor_sync(0xffffffffu, rmaxB, 2));

        float mnA = fmaxf(mA, rmaxA);
        float mnB = fmaxf(mB, rmaxB);
        float corrA = __expf(mA - mnA);
        float corrB = __expf(mB - mnB);

        float sumA = 0.f, sumB = 0.f;
        #pragma unroll
        for (int nt = 0; nt < 8; nt++) {
            s[nt][0] = __expf(s[nt][0] - mnA);
            s[nt][1] = __expf(s[nt][1] - mnA);
            s[nt][2] = __expf(s[nt][2] - mnB);
            s[nt][3] = __expf(s[nt][3] - mnB);
            sumA += s[nt][0] + s[nt][1];
            sumB += s[nt][2] + s[nt][3];
        }
        sumA += __shfl_xor_sync(0xffffffffu, sumA, 1);
        sumA += __shfl_xor_sync(0xffffffffu, sumA, 2);
        sumB += __shfl_xor_sync(0xffffffffu, sumB, 1);
        sumB += __shfl_xor_sync(0xffffffffu, sumB, 2);

        lA = lA * corrA + sumA;  mA = mnA;
        lB = lB * corrB + sumB;  mB = mnB;
        #pragma unroll
        for (int nt = 0; nt < 8; nt++) {
            o[nt][0] *= corrA;  o[nt][1] *= corrA;
            o[nt][2] *= corrB;  o[nt][3] *= corrB;
        }

        // Stage P (warp-private rows of QP)
        #pragma unroll
        for (int nt = 0; nt < 8; nt++) {
            *(float2*)&QP[(rA    ) * QSTR + nt * 8 + tig * 2] = make_float2(s[nt][0], s[nt][1]);
            *(float2*)&QP[(rA + 8) * QSTR + nt * 8 + tig * 2] = make_float2(s[nt][2], s[nt][3]);
        }
        __syncwarp();

        // O += P @ V
        #pragma unroll
        for (int ks = 0; ks < 8; ks++) {
            uint32_t pa0 = f2tf32(QP[(rA    ) * QSTR + ks * 8 + tig    ]);
            uint32_t pa1 = f2tf32(QP[(rA + 8) * QSTR + ks * 8 + tig    ]);
            uint32_t pa2 = f2tf32(QP[(rA    ) * QSTR + ks * 8 + tig + 4]);
            uint32_t pa3 = f2tf32(QP[(rA + 8) * QSTR + ks * 8 + tig + 4]);
            #pragma unroll
            for (int nt = 0; nt < 8; nt++) {
                uint32_t b0 = f2tf32(Vs[(ks * 8 + tig    ) * VSTR + nt * 8 + gid]);
                uint32_t b1 = f2tf32(Vs[(ks * 8 + tig + 4) * VSTR + nt * 8 + gid]);
                mma_tf32(o[nt], pa0, pa1, pa2, pa3, b0, b1);
            }
        }
        __syncthreads();   // all warps done with stage kt&1 before it is reloaded
    }

    // Finalize + write ctx (head-interleaved [B,S,D])
    float invA = 1.f / lA, invB = 1.f / lB;
    const size_t grA = baseRow + qt * 64 + wid * 16 + gid;
    #pragma unroll
    for (int nt = 0; nt < 8; nt++) {
        float2 v0 = make_float2(o[nt][0] * invA, o[nt][1] * invA);
        float2 v1 = make_float2(o[nt][2] * invB, o[nt][3] * invB);
        *(float2*)&ctx[grA * DD + hcol + nt * 8 + tig * 2]       = v0;
        *(float2*)&ctx[(grA + 8) * DD + hcol + nt * 8 + tig * 2] = v1;
    }
}

// ---------------------------------------------------------------------------
extern "C" void kernel_launch(void* const* d_in, const int* in_sizes, int n_in,
                              void* d_out, int out_size)
{
    const float* x  = (const float*)d_in[0];
    const float* WQ = (const float*)d_in[1];
    const float* WK = (const float*)d_in[2];
    const float* WV = (const float*)d_in[3];
    const float* WO = (const float*)d_in[4];
    float* out = (float*)d_out;

    float *Qp, *Kp, *Vp, *Cp;
    cudaGetSymbolAddress((void**)&Qp, g_Q);
    cudaGetSymbolAddress((void**)&Kp, g_K);
    cudaGetSymbolAddress((void**)&Vp, g_V);
    cudaGetSymbolAddress((void**)&Cp, g_ctx);

    cudaFuncSetAttribute(gemm_mma, cudaFuncAttributeMaxDynamicSharedMemorySize, GSMEM);
    cudaFuncSetAttribute(attn_mma, cudaFuncAttributeMaxDynamicSharedMemorySize, ASMEM);

    dim3 gg(DD / 128, MM / 128);    // (8, 64)
    gemm_mma<<<gg, 256, GSMEM>>>(x, WQ, Qp);
    gemm_mma<<<gg, 256, GSMEM>>>(x, WK, Kp);
    gemm_mma<<<gg, 256, GSMEM>>>(x, WV, Vp);

    dim3 gAttn(SS / 64, BB * HH);   // (32, 64)
    attn_mma<<<gAttn, 128, ASMEM>>>(Qp, Kp, Vp, Cp);

    gemm_mma<<<gg, 256, GSMEM>>>(Cp, WO, out);
}

// round 13
// speedup vs baseline: 3.6641x; 1.7824x over previous
#include <cuda_runtime.h>
#include <math_constants.h>
#include <cstdint>

#define BB 4
#define SS 2048
#define DD 1024
#define HH 16
#define DH 64
#define MM (BB*SS)          // 8192 rows

// Scratch (allocation-free rule: __device__ globals)
__device__ float g_Q[MM*DD];
__device__ float g_K[MM*DD];
__device__ float g_V[MM*DD];
__device__ float g_ctx[MM*DD];
__device__ float g_xt[MM*DD];
__device__ float g_WQt[DD*DD];
__device__ float g_WKt[DD*DD];
__device__ float g_WVt[DD*DD];
__device__ float g_WOt[DD*DD];

// ---------------------------------------------------------------------------
// Helpers (sm_80-era PTX: cp.async + mma.sync — valid on sm_103 target)
// ---------------------------------------------------------------------------
__device__ __forceinline__ uint32_t smem_addr(const void* p) {
    return (uint32_t)__cvta_generic_to_shared(p);
}
__device__ __forceinline__ void cp_async16(uint32_t saddr, const void* g) {
    asm volatile("cp.async.cg.shared.global [%0], [%1], 16;" :: "r"(saddr), "l"(g));
}
#define CP_COMMIT() asm volatile("cp.async.commit_group;" ::: "memory")
#define CP_WAIT(n)  asm volatile("cp.async.wait_group %0;" :: "n"(n) : "memory")

__device__ __forceinline__ uint32_t f2tf32(float f) {
    uint32_t r; asm("cvt.rna.tf32.f32 %0, %1;" : "=r"(r) : "f"(f)); return r;
}
__device__ __forceinline__ float ex2f(float x) {
    float r; asm("ex2.approx.f32 %0, %1;" : "=f"(r) : "f"(x)); return r;
}
__device__ __forceinline__ uint32_t ldsu(const float* p) {
    return __float_as_uint(*p);
}
__device__ __forceinline__ void mma_tf32(float c[4],
    uint32_t a0, uint32_t a1, uint32_t a2, uint32_t a3, uint32_t b0, uint32_t b1)
{
    asm volatile(
        "mma.sync.aligned.m16n8k8.row.col.f32.tf32.tf32.f32 "
        "{%0,%1,%2,%3}, {%4,%5,%6,%7}, {%8,%9}, {%0,%1,%2,%3};"
        : "+f"(c[0]), "+f"(c[1]), "+f"(c[2]), "+f"(c[3])
        : "r"(a0), "r"(a1), "r"(a2), "r"(a3), "r"(b0), "r"(b1));
}

// ---------------------------------------------------------------------------
// Elementwise tf32 pre-round (optionally scaled): out = tf32(in * scale)
// ---------------------------------------------------------------------------
__global__ __launch_bounds__(256) void round_tf32(
    const float* __restrict__ in, float* __restrict__ out, int n4, float scale)
{
    int i = blockIdx.x * blockDim.x + threadIdx.x;
    if (i < n4) {
        float4 v = *(const float4*)&in[i * 4];
        float4 o;
        o.x = __uint_as_float(f2tf32(v.x * scale));
        o.y = __uint_as_float(f2tf32(v.y * scale));
        o.z = __uint_as_float(f2tf32(v.z * scale));
        o.w = __uint_as_float(f2tf32(v.w * scale));
        *(float4*)&out[i * 4] = o;
    }
}

// ---------------------------------------------------------------------------
// tf32 tensor-core GEMM: C = A @ B. Inputs pre-rounded to tf32 bits -> raw
// fragment loads, zero cvt in mainloop. TF32OUT rounds the output (for
// buffers consumed by later raw-load GEMMs).
// ---------------------------------------------------------------------------
#define GBK 16
#define ASTR 20
#define BSTR 136
#define STAGES 3
#define A_BYTES (128*ASTR*4)
#define B_BYTES (GBK*BSTR*4)
#define STAGE_BYTES (A_BYTES + B_BYTES)
#define GSMEM (STAGES*STAGE_BYTES)

template<bool TF32OUT>
__global__ __launch_bounds__(256) void gemm_mma(
    const float* __restrict__ A, const float* __restrict__ B,
    float* __restrict__ C)
{
    extern __shared__ char smem[];
    const int tid   = threadIdx.x;
    const int wid   = tid >> 5;
    const int lane  = tid & 31;
    const int gid   = lane >> 2;
    const int tig   = lane & 3;
    const int wm    = wid & 1;
    const int wn    = wid >> 1;
    const int row0  = blockIdx.y * 128;
    const int col0  = blockIdx.x * 128;

    float c[4][4][4];
    #pragma unroll
    for (int i = 0; i < 4; i++)
        #pragma unroll
        for (int j = 0; j < 4; j++)
            #pragma unroll
            for (int r = 0; r < 4; r++) c[i][j][r] = 0.f;

    auto load_tile = [&](int buf, int kk) {
        char* base = smem + buf * STAGE_BYTES;
        #pragma unroll
        for (int i = 0; i < 2; i++) {
            int f  = tid + 256 * i;
            int r  = f >> 2;
            int k4 = (f & 3) * 4;
            cp_async16(smem_addr(base + (r * ASTR + k4) * 4),
                       &A[(size_t)(row0 + r) * DD + kk + k4]);
        }
        #pragma unroll
        for (int i = 0; i < 2; i++) {
            int f  = tid + 256 * i;
            int kr = f >> 5;
            int c4 = (f & 31) * 4;
            cp_async16(smem_addr(base + A_BYTES + (kr * BSTR + c4) * 4),
                       &B[(size_t)(kk + kr) * DD + col0 + c4]);
        }
    };

    const int NKT = DD / GBK;
    #pragma unroll
    for (int s = 0; s < STAGES - 1; s++) { load_tile(s, s * GBK); CP_COMMIT(); }

    for (int kt = 0; kt < NKT; kt++) {
        CP_WAIT(STAGES - 2);
        __syncthreads();

        if (kt + STAGES - 1 < NKT) load_tile((kt + STAGES - 1) % STAGES,
                                             (kt + STAGES - 1) * GBK);
        CP_COMMIT();

        const int buf = kt % STAGES;
        const float* As = (const float*)(smem + buf * STAGE_BYTES);
        const float* Bs = (const float*)(smem + buf * STAGE_BYTES + A_BYTES);

        #pragma unroll
        for (int s = 0; s < 2; s++) {
            uint32_t af[4][4], bf[4][2];
            #pragma unroll
            for (int i = 0; i < 4; i++) {
                int br = wm * 64 + i * 16;
                af[i][0] = ldsu(&As[(br + gid    ) * ASTR + s * 8 + tig    ]);
                af[i][1] = ldsu(&As[(br + gid + 8) * ASTR + s * 8 + tig    ]);
                af[i][2] = ldsu(&As[(br + gid    ) * ASTR + s * 8 + tig + 4]);
                af[i][3] = ldsu(&As[(br + gid + 8) * ASTR + s * 8 + tig + 4]);
            }
            #pragma unroll
            for (int j = 0; j < 4; j++) {
                int bc = wn * 32 + j * 8;
                bf[j][0] = ldsu(&Bs[(s * 8 + tig    ) * BSTR + bc + gid]);
                bf[j][1] = ldsu(&Bs[(s * 8 + tig + 4) * BSTR + bc + gid]);
            }
            #pragma unroll
            for (int i = 0; i < 4; i++)
                #pragma unroll
                for (int j = 0; j < 4; j++)
                    mma_tf32(c[i][j], af[i][0], af[i][1], af[i][2], af[i][3],
                             bf[j][0], bf[j][1]);
        }
        __syncthreads();
    }

    #pragma unroll
    for (int i = 0; i < 4; i++) {
        #pragma unroll
        for (int j = 0; j < 4; j++) {
            int r  = row0 + wm * 64 + i * 16 + gid;
            int cc = col0 + wn * 32 + j * 8 + tig * 2;
            float2 v0, v1;
            if (TF32OUT) {
                v0 = {__uint_as_float(f2tf32(c[i][j][0])), __uint_as_float(f2tf32(c[i][j][1]))};
                v1 = {__uint_as_float(f2tf32(c[i][j][2])), __uint_as_float(f2tf32(c[i][j][3]))};
            } else {
                v0 = {c[i][j][0], c[i][j][1]};
                v1 = {c[i][j][2], c[i][j][3]};
            }
            *(float2*)&C[(size_t)r * DD + cc]       = v0;
            *(float2*)&C[(size_t)(r + 8) * DD + cc] = v1;
        }
    }
}

// ---------------------------------------------------------------------------
// Flash attention, tf32 mma.sync, all operands pre-rounded -> raw loads.
// Q pre-scaled by (1/sqrt(D))*log2(e) via WQ prep, so softmax uses bare ex2.
// ---------------------------------------------------------------------------
#define KSTR 68
#define VSTR 72
#define QSTR 68
#define KVSTAGE (64*KSTR + 64*VSTR)
#define ASMEM ((2*KVSTAGE + 64*QSTR) * 4)    // 89088 bytes

__global__ __launch_bounds__(128, 2) void attn_mma(
    const float* __restrict__ Q, const float* __restrict__ K,
    const float* __restrict__ V, float* __restrict__ ctx)
{
    extern __shared__ float sm[];
    float* QP = sm + 2 * KVSTAGE;
    uint32_t* QPu = (uint32_t*)QP;

    const int tid  = threadIdx.x;
    const int wid  = tid >> 5;
    const int lane = tid & 31;
    const int gid  = lane >> 2;
    const int tig  = lane & 3;

    const int qt = blockIdx.x;
    const int bh = blockIdx.y;
    const int b  = bh / HH;
    const int h  = bh % HH;
    const size_t baseRow = (size_t)b * SS;
    const int    hcol    = h * DH;

    // Prologue: Q tile + K/V tile 0
    {
        #pragma unroll
        for (int i = 0; i < 8; i++) {
            int f  = tid + 128 * i;
            int r  = f >> 4;
            int c4 = (f & 15) * 4;
            cp_async16(smem_addr(&QP[r * QSTR + c4]),
                       &Q[(baseRow + qt * 64 + r) * DD + hcol + c4]);
            size_t gro = (baseRow + r) * DD + hcol + c4;
            cp_async16(smem_addr(&sm[r * KSTR + c4]), &K[gro]);
            cp_async16(smem_addr(&sm[64 * KSTR + r * VSTR + c4]), &V[gro]);
        }
        CP_COMMIT();
    }
    CP_WAIT(0);
    __syncthreads();

    // Persistent Q fragments (already scaled + tf32-rounded upstream)
    const int rA = wid * 16 + gid;
    uint32_t qf[8][4];
    #pragma unroll
    for (int ks = 0; ks < 8; ks++) {
        qf[ks][0] = QPu[(rA    ) * QSTR + ks * 8 + tig    ];
        qf[ks][1] = QPu[(rA + 8) * QSTR + ks * 8 + tig    ];
        qf[ks][2] = QPu[(rA    ) * QSTR + ks * 8 + tig + 4];
        qf[ks][3] = QPu[(rA + 8) * QSTR + ks * 8 + tig + 4];
    }

    float o[8][4];
    #pragma unroll
    for (int nt = 0; nt < 8; nt++)
        #pragma unroll
        for (int r = 0; r < 4; r++) o[nt][r] = 0.f;
    float mA = -CUDART_INF_F, mB = -CUDART_INF_F, lA = 0.f, lB = 0.f;

    const int NKT = SS / 64;
    for (int kt = 0; kt < NKT; kt++) {
        if (kt + 1 < NKT) {
            float* Kn = sm + ((kt + 1) & 1) * KVSTAGE;
            float* Vn = Kn + 64 * KSTR;
            #pragma unroll
            for (int i = 0; i < 8; i++) {
                int f  = tid + 128 * i;
                int r  = f >> 4;
                int c4 = (f & 15) * 4;
                size_t gro = (baseRow + (kt + 1) * 64 + r) * DD + hcol + c4;
                cp_async16(smem_addr(&Kn[r * KSTR + c4]), &K[gro]);
                cp_async16(smem_addr(&Vn[r * VSTR + c4]), &V[gro]);
            }
            CP_COMMIT();
            CP_WAIT(1);
        } else {
            CP_WAIT(0);
        }
        __syncthreads();

        const float* Ks = sm + (kt & 1) * KVSTAGE;
        const float* Vs = Ks + 64 * KSTR;

        // S = Q @ K^T  (log2-domain: Q pre-scaled by scale*log2e)
        float s[8][4];
        #pragma unroll
        for (int nt = 0; nt < 8; nt++)
            #pragma unroll
            for (int r = 0; r < 4; r++) s[nt][r] = 0.f;

        #pragma unroll
        for (int ks = 0; ks < 8; ks++) {
            #pragma unroll
            for (int nt = 0; nt < 8; nt++) {
                uint32_t b0 = ldsu(&Ks[(nt * 8 + gid) * KSTR + ks * 8 + tig    ]);
                uint32_t b1 = ldsu(&Ks[(nt * 8 + gid) * KSTR + ks * 8 + tig + 4]);
                mma_tf32(s[nt], qf[ks][0], qf[ks][1], qf[ks][2], qf[ks][3], b0, b1);
            }
        }

        // Online softmax (base-2 domain)
        float rmaxA = -CUDART_INF_F, rmaxB = -CUDART_INF_F;
        #pragma unroll
        for (int nt = 0; nt < 8; nt++) {
            rmaxA = fmaxf(rmaxA, fmaxf(s[nt][0], s[nt][1]));
            rmaxB = fmaxf(rmaxB, fmaxf(s[nt][2], s[nt][3]));
        }
        rmaxA = fmaxf(rmaxA, __shfl_xor_sync(0xffffffffu, rmaxA, 1));
        rmaxA = fmaxf(rmaxA, __shfl_xor_sync(0xffffffffu, rmaxA, 2));
        rmaxB = fmaxf(rmaxB, __shfl_xor_sync(0xffffffffu, rmaxB, 1));
        rmaxB = fmaxf(rmaxB, __shfl_xor_sync(0xffffffffu, rmaxB, 2));

        float mnA = fmaxf(mA, rmaxA);
        float mnB = fmaxf(mB, rmaxB);
        float corrA = ex2f(mA - mnA);
        float corrB = ex2f(mB - mnB);

        float sumA = 0.f, sumB = 0.f;
        #pragma unroll
        for (int nt = 0; nt < 8; nt++) {
            s[nt][0] = ex2f(s[nt][0] - mnA);
            s[nt][1] = ex2f(s[nt][1] - mnA);
            s[nt][2] = ex2f(s[nt][2] - mnB);
            s[nt][3] = ex2f(s[nt][3] - mnB);
            sumA += s[nt][0] + s[nt][1];
            sumB += s[nt][2] + s[nt][3];
        }
        sumA += __shfl_xor_sync(0xffffffffu, sumA, 1);
        sumA += __shfl_xor_sync(0xffffffffu, sumA, 2);
        sumB += __shfl_xor_sync(0xffffffffu, sumB, 1);
        sumB += __shfl_xor_sync(0xffffffffu, sumB, 2);

        lA = lA * corrA + sumA;  mA = mnA;
        lB = lB * corrB + sumB;  mB = mnB;
        #pragma unroll
        for (int nt = 0; nt < 8; nt++) {
            o[nt][0] *= corrA;  o[nt][1] *= corrA;
            o[nt][2] *= corrB;  o[nt][3] *= corrB;
        }

        // Stage P (tf32-rounded at store; warp-private rows)
        #pragma unroll
        for (int nt = 0; nt < 8; nt++) {
            uint2 p0 = {f2tf32(s[nt][0]), f2tf32(s[nt][1])};
            uint2 p1 = {f2tf32(s[nt][2]), f2tf32(s[nt][3])};
            *(uint2*)&QPu[(rA    ) * QSTR + nt * 8 + tig * 2] = p0;
            *(uint2*)&QPu[(rA + 8) * QSTR + nt * 8 + tig * 2] = p1;
        }
        __syncwarp();

        // O += P @ V
        #pragma unroll
        for (int ks = 0; ks < 8; ks++) {
            uint32_t pa0 = QPu[(rA    ) * QSTR + ks * 8 + tig    ];
            uint32_t pa1 = QPu[(rA + 8) * QSTR + ks * 8 + tig    ];
            uint32_t pa2 = QPu[(rA    ) * QSTR + ks * 8 + tig + 4];
            uint32_t pa3 = QPu[(rA + 8) * QSTR + ks * 8 + tig + 4];
            #pragma unroll
            for (int nt = 0; nt < 8; nt++) {
                uint32_t b0 = ldsu(&Vs[(ks * 8 + tig    ) * VSTR + nt * 8 + gid]);
                uint32_t b1 = ldsu(&Vs[(ks * 8 + tig + 4) * VSTR + nt * 8 + gid]);
                mma_tf32(o[nt], pa0, pa1, pa2, pa3, b0, b1);
            }
        }
        __syncthreads();
    }

    // Finalize, tf32-round (final GEMM raw-loads ctx), write head-interleaved
    float invA = 1.f / lA, invB = 1.f / lB;
    const size_t grA = baseRow + qt * 64 + wid * 16 + gid;
    #pragma unroll
    for (int nt = 0; nt < 8; nt++) {
        float2 v0 = {__uint_as_float(f2tf32(o[nt][0] * invA)),
                     __uint_as_float(f2tf32(o[nt][1] * invA))};
        float2 v1 = {__uint_as_float(f2tf32(o[nt][2] * invB)),
                     __uint_as_float(f2tf32(o[nt][3] * invB))};
        *(float2*)&ctx[grA * DD + hcol + nt * 8 + tig * 2]       = v0;
        *(float2*)&ctx[(grA + 8) * DD + hcol + nt * 8 + tig * 2] = v1;
    }
}

// ---------------------------------------------------------------------------
extern "C" void kernel_launch(void* const* d_in, const int* in_sizes, int n_in,
                              void* d_out, int out_size)
{
    const float* x  = (const float*)d_in[0];
    const float* WQ = (const float*)d_in[1];
    const float* WK = (const float*)d_in[2];
    const float* WV = (const float*)d_in[3];
    const float* WO = (const float*)d_in[4];
    float* out = (float*)d_out;

    float *Qp, *Kp, *Vp, *Cp, *xt, *wq, *wk, *wv, *wo;
    cudaGetSymbolAddress((void**)&Qp, g_Q);
    cudaGetSymbolAddress((void**)&Kp, g_K);
    cudaGetSymbolAddress((void**)&Vp, g_V);
    cudaGetSymbolAddress((void**)&Cp, g_ctx);
    cudaGetSymbolAddress((void**)&xt, g_xt);
    cudaGetSymbolAddress((void**)&wq, g_WQt);
    cudaGetSymbolAddress((void**)&wk, g_WKt);
    cudaGetSymbolAddress((void**)&wv, g_WVt);
    cudaGetSymbolAddress((void**)&wo, g_WOt);

    cudaFuncSetAttribute(gemm_mma<true>,  cudaFuncAttributeMaxDynamicSharedMemorySize, GSMEM);
    cudaFuncSetAttribute(gemm_mma<false>, cudaFuncAttributeMaxDynamicSharedMemorySize, GSMEM);
    cudaFuncSetAttribute(attn_mma, cudaFuncAttributeMaxDynamicSharedMemorySize, ASMEM);

    // Pre-round inputs to tf32. Q-weight carries softmax scale * log2(e).
    const float qscale = 0.03125f * 1.4426950408889634f;
    round_tf32<<<(MM*DD/4 + 255)/256, 256>>>(x,  xt, MM*DD/4, 1.f);
    round_tf32<<<(DD*DD/4 + 255)/256, 256>>>(WQ, wq, DD*DD/4, qscale);
    round_tf32<<<(DD*DD/4 + 255)/256, 256>>>(WK, wk, DD*DD/4, 1.f);
    round_tf32<<<(DD*DD/4 + 255)/256, 256>>>(WV, wv, DD*DD/4, 1.f);
    round_tf32<<<(DD*DD/4 + 255)/256, 256>>>(WO, wo, DD*DD/4, 1.f);

    dim3 gg(DD / 128, MM / 128);    // (8, 64)
    gemm_mma<true><<<gg, 256, GSMEM>>>(xt, wq, Qp);
    gemm_mma<true><<<gg, 256, GSMEM>>>(xt, wk, Kp);
    gemm_mma<true><<<gg, 256, GSMEM>>>(xt, wv, Vp);

    dim3 gAttn(SS / 64, BB * HH);   // (32, 64)
    attn_mma<<<gAttn, 128, ASMEM>>>(Qp, Kp, Vp, Cp);

    gemm_mma<false><<<gg, 256, GSMEM>>>(Cp, wo, out);
}

// round 14
// speedup vs baseline: 3.7002x; 1.0098x over previous
#include <cuda_runtime.h>
#include <math_constants.h>
#include <cstdint>

#define BB 4
#define SS 2048
#define DD 1024
#define HH 16
#define DH 64
#define MM (BB*SS)          // 8192 rows

// Scratch (allocation-free rule: __device__ globals)
__device__ float g_Q[MM*DD];
__device__ float g_K[MM*DD];
__device__ float g_V[MM*DD];
__device__ float g_ctx[MM*DD];
__device__ float g_xt[MM*DD];
__device__ float g_WQt[DD*DD];
__device__ float g_WKt[DD*DD];
__device__ float g_WVt[DD*DD];
__device__ float g_WOt[DD*DD];

// ---------------------------------------------------------------------------
// Helpers (sm_80-era PTX: cp.async + mma.sync — valid on sm_103 target)
// ---------------------------------------------------------------------------
__device__ __forceinline__ uint32_t smem_addr(const void* p) {
    return (uint32_t)__cvta_generic_to_shared(p);
}
__device__ __forceinline__ void cp_async16(uint32_t saddr, const void* g) {
    asm volatile("cp.async.cg.shared.global [%0], [%1], 16;" :: "r"(saddr), "l"(g));
}
#define CP_COMMIT() asm volatile("cp.async.commit_group;" ::: "memory")
#define CP_WAIT(n)  asm volatile("cp.async.wait_group %0;" :: "n"(n) : "memory")

__device__ __forceinline__ uint32_t f2tf32(float f) {
    uint32_t r; asm("cvt.rna.tf32.f32 %0, %1;" : "=r"(r) : "f"(f)); return r;
}
__device__ __forceinline__ float ex2f(float x) {
    float r; asm("ex2.approx.f32 %0, %1;" : "=f"(r) : "f"(x)); return r;
}
__device__ __forceinline__ uint32_t ldsu(const float* p) {
    return __float_as_uint(*p);
}
__device__ __forceinline__ void mma_tf32(float c[4],
    uint32_t a0, uint32_t a1, uint32_t a2, uint32_t a3, uint32_t b0, uint32_t b1)
{
    asm volatile(
        "mma.sync.aligned.m16n8k8.row.col.f32.tf32.tf32.f32 "
        "{%0,%1,%2,%3}, {%4,%5,%6,%7}, {%8,%9}, {%0,%1,%2,%3};"
        : "+f"(c[0]), "+f"(c[1]), "+f"(c[2]), "+f"(c[3])
        : "r"(a0), "r"(a1), "r"(a2), "r"(a3), "r"(b0), "r"(b1));
}

// ---------------------------------------------------------------------------
// Elementwise tf32 pre-round (optionally scaled): out = tf32(in * scale)
// ---------------------------------------------------------------------------
__global__ __launch_bounds__(256) void round_tf32(
    const float* __restrict__ in, float* __restrict__ out, int n4, float scale)
{
    int i = blockIdx.x * blockDim.x + threadIdx.x;
    if (i < n4) {
        float4 v = *(const float4*)&in[i * 4];
        float4 o;
        o.x = __uint_as_float(f2tf32(v.x * scale));
        o.y = __uint_as_float(f2tf32(v.y * scale));
        o.z = __uint_as_float(f2tf32(v.z * scale));
        o.w = __uint_as_float(f2tf32(v.w * scale));
        *(float4*)&out[i * 4] = o;
    }
}

// ---------------------------------------------------------------------------
// tf32 tensor-core GEMM (unchanged from R13): C = A @ B, raw fragment loads.
// ---------------------------------------------------------------------------
#define GBK 16
#define ASTR 20
#define BSTR 136
#define STAGES 3
#define A_BYTES (128*ASTR*4)
#define B_BYTES (GBK*BSTR*4)
#define STAGE_BYTES (A_BYTES + B_BYTES)
#define GSMEM (STAGES*STAGE_BYTES)

template<bool TF32OUT>
__global__ __launch_bounds__(256) void gemm_mma(
    const float* __restrict__ A, const float* __restrict__ B,
    float* __restrict__ C)
{
    extern __shared__ char smem[];
    const int tid   = threadIdx.x;
    const int wid   = tid >> 5;
    const int lane  = tid & 31;
    const int gid   = lane >> 2;
    const int tig   = lane & 3;
    const int wm    = wid & 1;
    const int wn    = wid >> 1;
    const int row0  = blockIdx.y * 128;
    const int col0  = blockIdx.x * 128;

    float c[4][4][4];
    #pragma unroll
    for (int i = 0; i < 4; i++)
        #pragma unroll
        for (int j = 0; j < 4; j++)
            #pragma unroll
            for (int r = 0; r < 4; r++) c[i][j][r] = 0.f;

    auto load_tile = [&](int buf, int kk) {
        char* base = smem + buf * STAGE_BYTES;
        #pragma unroll
        for (int i = 0; i < 2; i++) {
            int f  = tid + 256 * i;
            int r  = f >> 2;
            int k4 = (f & 3) * 4;
            cp_async16(smem_addr(base + (r * ASTR + k4) * 4),
                       &A[(size_t)(row0 + r) * DD + kk + k4]);
        }
        #pragma unroll
        for (int i = 0; i < 2; i++) {
            int f  = tid + 256 * i;
            int kr = f >> 5;
            int c4 = (f & 31) * 4;
            cp_async16(smem_addr(base + A_BYTES + (kr * BSTR + c4) * 4),
                       &B[(size_t)(kk + kr) * DD + col0 + c4]);
        }
    };

    const int NKT = DD / GBK;
    #pragma unroll
    for (int s = 0; s < STAGES - 1; s++) { load_tile(s, s * GBK); CP_COMMIT(); }

    for (int kt = 0; kt < NKT; kt++) {
        CP_WAIT(STAGES - 2);
        __syncthreads();

        if (kt + STAGES - 1 < NKT) load_tile((kt + STAGES - 1) % STAGES,
                                             (kt + STAGES - 1) * GBK);
        CP_COMMIT();

        const int buf = kt % STAGES;
        const float* As = (const float*)(smem + buf * STAGE_BYTES);
        const float* Bs = (const float*)(smem + buf * STAGE_BYTES + A_BYTES);

        #pragma unroll
        for (int s = 0; s < 2; s++) {
            uint32_t af[4][4], bf[4][2];
            #pragma unroll
            for (int i = 0; i < 4; i++) {
                int br = wm * 64 + i * 16;
                af[i][0] = ldsu(&As[(br + gid    ) * ASTR + s * 8 + tig    ]);
                af[i][1] = ldsu(&As[(br + gid + 8) * ASTR + s * 8 + tig    ]);
                af[i][2] = ldsu(&As[(br + gid    ) * ASTR + s * 8 + tig + 4]);
                af[i][3] = ldsu(&As[(br + gid + 8) * ASTR + s * 8 + tig + 4]);
            }
            #pragma unroll
            for (int j = 0; j < 4; j++) {
                int bc = wn * 32 + j * 8;
                bf[j][0] = ldsu(&Bs[(s * 8 + tig    ) * BSTR + bc + gid]);
                bf[j][1] = ldsu(&Bs[(s * 8 + tig + 4) * BSTR + bc + gid]);
            }
            #pragma unroll
            for (int i = 0; i < 4; i++)
                #pragma unroll
                for (int j = 0; j < 4; j++)
                    mma_tf32(c[i][j], af[i][0], af[i][1], af[i][2], af[i][3],
                             bf[j][0], bf[j][1]);
        }
        __syncthreads();
    }

    #pragma unroll
    for (int i = 0; i < 4; i++) {
        #pragma unroll
        for (int j = 0; j < 4; j++) {
            int r  = row0 + wm * 64 + i * 16 + gid;
            int cc = col0 + wn * 32 + j * 8 + tig * 2;
            float2 v0, v1;
            if (TF32OUT) {
                v0 = {__uint_as_float(f2tf32(c[i][j][0])), __uint_as_float(f2tf32(c[i][j][1]))};
                v1 = {__uint_as_float(f2tf32(c[i][j][2])), __uint_as_float(f2tf32(c[i][j][3]))};
            } else {
                v0 = {c[i][j][0], c[i][j][1]};
                v1 = {c[i][j][2], c[i][j][3]};
            }
            *(float2*)&C[(size_t)r * DD + cc]       = v0;
            *(float2*)&C[(size_t)(r + 8) * DD + cc] = v1;
        }
    }
}

// ---------------------------------------------------------------------------
// Flash attention, tf32 mma.sync. BM=128 q-rows/CTA, 4 warps, each warp owns
// 32 rows (two 16-row m-tiles) so every K/V b-fragment feeds 2 MMAs.
// Q persistent in regs (pre-scaled by scale*log2e upstream); Q smem region
// recycled for P. Raw fragment loads everywhere; base-2 softmax.
// ---------------------------------------------------------------------------
#define KSTR 68
#define VSTR 72
#define QSTR 68
#define ABM 128
#define KVSTAGE (64*KSTR + 64*VSTR)              // 8960 floats
#define ASMEM ((2*KVSTAGE + ABM*QSTR) * 4)       // 106496 bytes

__global__ __launch_bounds__(128, 2) void attn_mma(
    const float* __restrict__ Q, const float* __restrict__ K,
    const float* __restrict__ V, float* __restrict__ ctx)
{
    extern __shared__ float sm[];
    float* QP = sm + 2 * KVSTAGE;
    uint32_t* QPu = (uint32_t*)QP;

    const int tid  = threadIdx.x;
    const int wid  = tid >> 5;
    const int lane = tid & 31;
    const int gid  = lane >> 2;
    const int tig  = lane & 3;

    const int qt = blockIdx.x;
    const int bh = blockIdx.y;
    const int b  = bh / HH;
    const int h  = bh % HH;
    const size_t baseRow = (size_t)b * SS;
    const int    hcol    = h * DH;

    // Prologue: Q tile (128 rows) + K/V tile 0 (64 keys)
    {
        #pragma unroll
        for (int i = 0; i < 16; i++) {
            int f  = tid + 128 * i;          // 0..2047
            int r  = f >> 4;                 // 0..127
            int c4 = (f & 15) * 4;
            cp_async16(smem_addr(&QP[r * QSTR + c4]),
                       &Q[(baseRow + qt * ABM + r) * DD + hcol + c4]);
        }
        #pragma unroll
        for (int i = 0; i < 8; i++) {
            int f  = tid + 128 * i;          // 0..1023
            int r  = f >> 4;                 // 0..63
            int c4 = (f & 15) * 4;
            size_t gro = (baseRow + r) * DD + hcol + c4;
            cp_async16(smem_addr(&sm[r * KSTR + c4]), &K[gro]);
            cp_async16(smem_addr(&sm[64 * KSTR + r * VSTR + c4]), &V[gro]);
        }
        CP_COMMIT();
    }
    CP_WAIT(0);
    __syncthreads();

    // Persistent Q fragments for both m-tiles (already scaled + rounded)
    const int r0 = wid * 32 + gid;           // m-tile 0 base row
    uint32_t qf[2][8][4];
    #pragma unroll
    for (int mt = 0; mt < 2; mt++) {
        int rr = r0 + mt * 16;
        #pragma unroll
        for (int ks = 0; ks < 8; ks++) {
            qf[mt][ks][0] = QPu[(rr    ) * QSTR + ks * 8 + tig    ];
            qf[mt][ks][1] = QPu[(rr + 8) * QSTR + ks * 8 + tig    ];
            qf[mt][ks][2] = QPu[(rr    ) * QSTR + ks * 8 + tig + 4];
            qf[mt][ks][3] = QPu[(rr + 8) * QSTR + ks * 8 + tig + 4];
        }
    }
    __syncwarp();   // all qf reads done before QP rows are reused for P

    float o[2][8][4];
    float m[2][2], l[2][2];
    #pragma unroll
    for (int mt = 0; mt < 2; mt++) {
        m[mt][0] = -CUDART_INF_F; m[mt][1] = -CUDART_INF_F;
        l[mt][0] = 0.f;           l[mt][1] = 0.f;
        #pragma unroll
        for (int nt = 0; nt < 8; nt++)
            #pragma unroll
            for (int r = 0; r < 4; r++) o[mt][nt][r] = 0.f;
    }

    const int NKT = SS / 64;
    for (int kt = 0; kt < NKT; kt++) {
        if (kt + 1 < NKT) {
            float* Kn = sm + ((kt + 1) & 1) * KVSTAGE;
            float* Vn = Kn + 64 * KSTR;
            #pragma unroll
            for (int i = 0; i < 8; i++) {
                int f  = tid + 128 * i;
                int r  = f >> 4;
                int c4 = (f & 15) * 4;
                size_t gro = (baseRow + (kt + 1) * 64 + r) * DD + hcol + c4;
                cp_async16(smem_addr(&Kn[r * KSTR + c4]), &K[gro]);
                cp_async16(smem_addr(&Vn[r * VSTR + c4]), &V[gro]);
            }
            CP_COMMIT();
            CP_WAIT(1);
        } else {
            CP_WAIT(0);
        }
        __syncthreads();

        const float* Ks = sm + (kt & 1) * KVSTAGE;
        const float* Vs = Ks + 64 * KSTR;

        // S = Q @ K^T : every b-frag feeds both m-tiles
        float s[2][8][4];
        #pragma unroll
        for (int mt = 0; mt < 2; mt++)
            #pragma unroll
            for (int nt = 0; nt < 8; nt++)
                #pragma unroll
                for (int r = 0; r < 4; r++) s[mt][nt][r] = 0.f;

        #pragma unroll
        for (int ks = 0; ks < 8; ks++) {
            #pragma unroll
            for (int nt = 0; nt < 8; nt++) {
                uint32_t b0 = ldsu(&Ks[(nt * 8 + gid) * KSTR + ks * 8 + tig    ]);
                uint32_t b1 = ldsu(&Ks[(nt * 8 + gid) * KSTR + ks * 8 + tig + 4]);
                mma_tf32(s[0][nt], qf[0][ks][0], qf[0][ks][1], qf[0][ks][2], qf[0][ks][3], b0, b1);
                mma_tf32(s[1][nt], qf[1][ks][0], qf[1][ks][1], qf[1][ks][2], qf[1][ks][3], b0, b1);
            }
        }

        // Online softmax (base-2), per m-tile
        #pragma unroll
        for (int mt = 0; mt < 2; mt++) {
            float rmaxA = -CUDART_INF_F, rmaxB = -CUDART_INF_F;
            #pragma unroll
            for (int nt = 0; nt < 8; nt++) {
                rmaxA = fmaxf(rmaxA, fmaxf(s[mt][nt][0], s[mt][nt][1]));
                rmaxB = fmaxf(rmaxB, fmaxf(s[mt][nt][2], s[mt][nt][3]));
            }
            rmaxA = fmaxf(rmaxA, __shfl_xor_sync(0xffffffffu, rmaxA, 1));
            rmaxA = fmaxf(rmaxA, __shfl_xor_sync(0xffffffffu, rmaxA, 2));
            rmaxB = fmaxf(rmaxB, __shfl_xor_sync(0xffffffffu, rmaxB, 1));
            rmaxB = fmaxf(rmaxB, __shfl_xor_sync(0xffffffffu, rmaxB, 2));

            float mnA = fmaxf(m[mt][0], rmaxA);
            float mnB = fmaxf(m[mt][1], rmaxB);
            float corrA = ex2f(m[mt][0] - mnA);
            float corrB = ex2f(m[mt][1] - mnB);

            float sumA = 0.f, sumB = 0.f;
            #pragma unroll
            for (int nt = 0; nt < 8; nt++) {
                s[mt][nt][0] = ex2f(s[mt][nt][0] - mnA);
                s[mt][nt][1] = ex2f(s[mt][nt][1] - mnA);
                s[mt][nt][2] = ex2f(s[mt][nt][2] - mnB);
                s[mt][nt][3] = ex2f(s[mt][nt][3] - mnB);
                sumA += s[mt][nt][0] + s[mt][nt][1];
                sumB += s[mt][nt][2] + s[mt][nt][3];
            }
            sumA += __shfl_xor_sync(0xffffffffu, sumA, 1);
            sumA += __shfl_xor_sync(0xffffffffu, sumA, 2);
            sumB += __shfl_xor_sync(0xffffffffu, sumB, 1);
            sumB += __shfl_xor_sync(0xffffffffu, sumB, 2);

            l[mt][0] = l[mt][0] * corrA + sumA;  m[mt][0] = mnA;
            l[mt][1] = l[mt][1] * corrB + sumB;  m[mt][1] = mnB;
            #pragma unroll
            for (int nt = 0; nt < 8; nt++) {
                o[mt][nt][0] *= corrA;  o[mt][nt][1] *= corrA;
                o[mt][nt][2] *= corrB;  o[mt][nt][3] *= corrB;
            }
        }

        // Stage P (tf32-rounded; warp-private rows)
        #pragma unroll
        for (int mt = 0; mt < 2; mt++) {
            int rr = r0 + mt * 16;
            #pragma unroll
            for (int nt = 0; nt < 8; nt++) {
                uint2 p0 = {f2tf32(s[mt][nt][0]), f2tf32(s[mt][nt][1])};
                uint2 p1 = {f2tf32(s[mt][nt][2]), f2tf32(s[mt][nt][3])};
                *(uint2*)&QPu[(rr    ) * QSTR + nt * 8 + tig * 2] = p0;
                *(uint2*)&QPu[(rr + 8) * QSTR + nt * 8 + tig * 2] = p1;
            }
        }
        __syncwarp();

        // O += P @ V : b-frags shared across both m-tiles
        #pragma unroll
        for (int ks = 0; ks < 8; ks++) {
            uint32_t pa[2][4];
            #pragma unroll
            for (int mt = 0; mt < 2; mt++) {
                int rr = r0 + mt * 16;
                pa[mt][0] = QPu[(rr    ) * QSTR + ks * 8 + tig    ];
                pa[mt][1] = QPu[(rr + 8) * QSTR + ks * 8 + tig    ];
                pa[mt][2] = QPu[(rr    ) * QSTR + ks * 8 + tig + 4];
                pa[mt][3] = QPu[(rr + 8) * QSTR + ks * 8 + tig + 4];
            }
            #pragma unroll
            for (int nt = 0; nt < 8; nt++) {
                uint32_t b0 = ldsu(&Vs[(ks * 8 + tig    ) * VSTR + nt * 8 + gid]);
                uint32_t b1 = ldsu(&Vs[(ks * 8 + tig + 4) * VSTR + nt * 8 + gid]);
                mma_tf32(o[0][nt], pa[0][0], pa[0][1], pa[0][2], pa[0][3], b0, b1);
                mma_tf32(o[1][nt], pa[1][0], pa[1][1], pa[1][2], pa[1][3], b0, b1);
            }
        }
        __syncthreads();
    }

    // Finalize, tf32-round (final GEMM raw-loads ctx), write head-interleaved
    #pragma unroll
    for (int mt = 0; mt < 2; mt++) {
        float invA = 1.f / l[mt][0], invB = 1.f / l[mt][1];
        const size_t gr = baseRow + qt * ABM + wid * 32 + mt * 16 + gid;
        #pragma unroll
        for (int nt = 0; nt < 8; nt++) {
            float2 v0 = {__uint_as_float(f2tf32(o[mt][nt][0] * invA)),
                         __uint_as_float(f2tf32(o[mt][nt][1] * invA))};
            float2 v1 = {__uint_as_float(f2tf32(o[mt][nt][2] * invB)),
                         __uint_as_float(f2tf32(o[mt][nt][3] * invB))};
            *(float2*)&ctx[gr * DD + hcol + nt * 8 + tig * 2]       = v0;
            *(float2*)&ctx[(gr + 8) * DD + hcol + nt * 8 + tig * 2] = v1;
        }
    }
}

// ---------------------------------------------------------------------------
extern "C" void kernel_launch(void* const* d_in, const int* in_sizes, int n_in,
                              void* d_out, int out_size)
{
    const float* x  = (const float*)d_in[0];
    const float* WQ = (const float*)d_in[1];
    const float* WK = (const float*)d_in[2];
    const float* WV = (const float*)d_in[3];
    const float* WO = (const float*)d_in[4];
    float* out = (float*)d_out;

    float *Qp, *Kp, *Vp, *Cp, *xt, *wq, *wk, *wv, *wo;
    cudaGetSymbolAddress((void**)&Qp, g_Q);
    cudaGetSymbolAddress((void**)&Kp, g_K);
    cudaGetSymbolAddress((void**)&Vp, g_V);
    cudaGetSymbolAddress((void**)&Cp, g_ctx);
    cudaGetSymbolAddress((void**)&xt, g_xt);
    cudaGetSymbolAddress((void**)&wq, g_WQt);
    cudaGetSymbolAddress((void**)&wk, g_WKt);
    cudaGetSymbolAddress((void**)&wv, g_WVt);
    cudaGetSymbolAddress((void**)&wo, g_WOt);

    cudaFuncSetAttribute(gemm_mma<true>,  cudaFuncAttributeMaxDynamicSharedMemorySize, GSMEM);
    cudaFuncSetAttribute(gemm_mma<false>, cudaFuncAttributeMaxDynamicSharedMemorySize, GSMEM);
    cudaFuncSetAttribute(attn_mma, cudaFuncAttributeMaxDynamicSharedMemorySize, ASMEM);

    // Pre-round inputs to tf32. Q-weight carries softmax scale * log2(e).
    const float qscale = 0.03125f * 1.4426950408889634f;
    round_tf32<<<(MM*DD/4 + 255)/256, 256>>>(x,  xt, MM*DD/4, 1.f);
    round_tf32<<<(DD*DD/4 + 255)/256, 256>>>(WQ, wq, DD*DD/4, qscale);
    round_tf32<<<(DD*DD/4 + 255)/256, 256>>>(WK, wk, DD*DD/4, 1.f);
    round_tf32<<<(DD*DD/4 + 255)/256, 256>>>(WV, wv, DD*DD/4, 1.f);
    round_tf32<<<(DD*DD/4 + 255)/256, 256>>>(WO, wo, DD*DD/4, 1.f);

    dim3 gg(DD / 128, MM / 128);    // (8, 64)
    gemm_mma<true><<<gg, 256, GSMEM>>>(xt, wq, Qp);
    gemm_mma<true><<<gg, 256, GSMEM>>>(xt, wk, Kp);
    gemm_mma<true><<<gg, 256, GSMEM>>>(xt, wv, Vp);

    dim3 gAttn(SS / ABM, BB * HH);  // (16, 64)
    attn_mma<<<gAttn, 128, ASMEM>>>(Qp, Kp, Vp, Cp);

    gemm_mma<false><<<gg, 256, GSMEM>>>(Cp, wo, out);
}